// round 1
// baseline (speedup 1.0000x reference)
#include <cuda_runtime.h>

#define L_TOTAL 32768
#define KQ      1024
#define EDIM    64
#define CHUNK   128
#define THREADS 128

// ||e_k||^2 scratch (no cudaMalloc allowed)
__device__ float g_c[KQ];

__device__ __forceinline__ unsigned long long pk2(float a, float b) {
    unsigned long long r;
    asm("mov.b64 %0, {%1, %2};" : "=l"(r) : "f"(a), "f"(b));
    return r;
}
__device__ __forceinline__ void upk2(unsigned long long v, float& a, float& b) {
    asm("mov.b64 {%0, %1}, %2;" : "=f"(a), "=f"(b) : "l"(v));
}
// Blackwell packed fp32x2 FMA (2 MACs per issue on the fma pipe)
__device__ __forceinline__ unsigned long long fma2(unsigned long long a,
                                                   unsigned long long b,
                                                   unsigned long long c) {
    unsigned long long d;
    asm("fma.rn.f32x2 %0, %1, %2, %3;" : "=l"(d) : "l"(a), "l"(b), "l"(c));
    return d;
}
__device__ __forceinline__ unsigned long long add2(unsigned long long a,
                                                   unsigned long long b) {
    unsigned long long d;
    asm("add.rn.f32x2 %0, %1, %2;" : "=l"(d) : "l"(a), "l"(b));
    return d;
}

__global__ void vq_cnorm_kernel(const float* __restrict__ emb) {
    int k = blockIdx.x * blockDim.x + threadIdx.x;
    if (k < KQ) {
        const float4* row = reinterpret_cast<const float4*>(emb + k * EDIM);
        float s = 0.f;
        #pragma unroll
        for (int i = 0; i < EDIM / 4; i++) {
            float4 v = row[i];
            s += v.x * v.x + v.y * v.y + v.z * v.z + v.w * v.w;
        }
        g_c[k] = s;
    }
}

__global__ void __launch_bounds__(THREADS)
vq_main_kernel(const float* __restrict__ x,
               const float* __restrict__ emb,
               float* __restrict__ out) {
    __shared__ float4 se[CHUNK * (EDIM / 4)];   // 32 KB embedding chunk
    __shared__ float  sc[CHUNK];                // ||e||^2 chunk
    __shared__ int    sidx[THREADS];            // per-latent argmin

    const int tid   = threadIdx.x;
    const int lbase = blockIdx.x * THREADS;
    const int l     = lbase + tid;

    // Load this thread's latent row into registers as 32 f32x2 values.
    unsigned long long xr[EDIM / 2];
    {
        const float4* xrow = reinterpret_cast<const float4*>(x + (size_t)l * EDIM);
        #pragma unroll
        for (int i = 0; i < EDIM / 4; i++) {
            float4 v = xrow[i];
            xr[2 * i]     = pk2(v.x, v.y);
            xr[2 * i + 1] = pk2(v.z, v.w);
        }
    }

    float best = 3.4e38f;
    int   bidx = 0;

    for (int c0 = 0; c0 < KQ; c0 += CHUNK) {
        __syncthreads();  // previous chunk fully consumed
        // Cooperative, coalesced stage of CHUNK embedding rows into smem.
        const float4* src = reinterpret_cast<const float4*>(emb + (size_t)c0 * EDIM);
        #pragma unroll
        for (int i = 0; i < (CHUNK * (EDIM / 4)) / THREADS; i++)
            se[tid + i * THREADS] = src[tid + i * THREADS];
        if (tid < CHUNK) sc[tid] = g_c[c0 + tid];
        __syncthreads();

        #pragma unroll 1
        for (int k = 0; k < CHUNK; k++) {
            const float4* e4 = &se[k * (EDIM / 4)];
            unsigned long long a0 = 0ull, a1 = 0ull, a2 = 0ull, a3 = 0ull;
            #pragma unroll
            for (int j = 0; j < 8; j++) {
                float4 va = e4[2 * j];
                float4 vb = e4[2 * j + 1];
                a0 = fma2(xr[4 * j + 0], pk2(va.x, va.y), a0);
                a1 = fma2(xr[4 * j + 1], pk2(va.z, va.w), a1);
                a2 = fma2(xr[4 * j + 2], pk2(vb.x, vb.y), a2);
                a3 = fma2(xr[4 * j + 3], pk2(vb.z, vb.w), a3);
            }
            unsigned long long s = add2(add2(a0, a1), add2(a2, a3));
            float slo, shi;
            upk2(s, slo, shi);
            float dot   = slo + shi;
            float score = fmaf(-2.0f, dot, sc[k]);   // ||e||^2 - 2 x.e
            if (score < best) { best = score; bidx = c0 + k; }
        }
    }

    sidx[tid] = bidx;
    __syncthreads();

    // Coalesced epilogue: out = [x | quantized | z_hat | indices], all fp32.
    const size_t LE = (size_t)L_TOTAL * EDIM;
    #pragma unroll 4
    for (int i = tid; i < THREADS * EDIM; i += THREADS) {
        int li = i >> 6;          // latent within block
        int e  = i & (EDIM - 1);
        size_t goff = (size_t)(lbase + li) * EDIM + e;
        float xv = x[goff];
        float qv = emb[(size_t)sidx[li] * EDIM + e];
        out[goff]          = xv;
        out[LE + goff]     = qv;
        out[2 * LE + goff] = (xv + qv) - xv;   // mirror x + q - stop_grad(x)
    }
    out[3 * LE + lbase + tid] = (float)bidx;
}

extern "C" void kernel_launch(void* const* d_in, const int* in_sizes, int n_in,
                              void* d_out, int out_size) {
    const float* x   = (const float*)d_in[0];
    const float* emb = (const float*)d_in[1];
    float* out       = (float*)d_out;

    vq_cnorm_kernel<<<(KQ + 255) / 256, 256>>>(emb);
    vq_main_kernel<<<L_TOTAL / THREADS, THREADS>>>(x, emb, out);
}

// round 2
// speedup vs baseline: 1.2226x; 1.2226x over previous
#include <cuda_runtime.h>

#define L_TOTAL 32768
#define KQ      1024
#define EDIM    64
#define NWARP   4          // warps per block = k-split factor
#define KRANGE  (KQ / NWARP)   // 256 codes per warp
#define CH      32             // codes staged per chunk per warp
#define THREADS (NWARP * 32)

// ||e_k||^2 scratch (no cudaMalloc allowed)
__device__ float g_c[KQ];

__device__ __forceinline__ void upk2(unsigned long long v, float& a, float& b) {
    asm("mov.b64 {%0, %1}, %2;" : "=f"(a), "=f"(b) : "l"(v));
}
// Blackwell packed fp32x2 FMA (2 MACs per issue on the fma pipe)
__device__ __forceinline__ unsigned long long fma2(unsigned long long a,
                                                   unsigned long long b,
                                                   unsigned long long c) {
    unsigned long long d;
    asm("fma.rn.f32x2 %0, %1, %2, %3;" : "=l"(d) : "l"(a), "l"(b), "l"(c));
    return d;
}
__device__ __forceinline__ unsigned long long add2(unsigned long long a,
                                                   unsigned long long b) {
    unsigned long long d;
    asm("add.rn.f32x2 %0, %1, %2;" : "=l"(d) : "l"(a), "l"(b));
    return d;
}

__global__ void vq_cnorm_kernel(const float* __restrict__ emb) {
    int k = blockIdx.x * blockDim.x + threadIdx.x;
    if (k < KQ) {
        const float4* row = reinterpret_cast<const float4*>(emb + k * EDIM);
        float s = 0.f;
        #pragma unroll
        for (int i = 0; i < EDIM / 4; i++) {
            float4 v = row[i];
            s += v.x * v.x + v.y * v.y + v.z * v.z + v.w * v.w;
        }
        g_c[k] = s;
    }
}

__global__ void __launch_bounds__(THREADS, 4)
vq_main_kernel(const float* __restrict__ x,
               const float* __restrict__ emb,
               float* __restrict__ out) {
    // Per-warp private staging: CH codes x 64 floats each (8 KB per warp)
    __shared__ float se[NWARP][CH * EDIM];
    __shared__ float sc[NWARP][CH];
    __shared__ float rbest[NWARP][32];
    __shared__ int   ridx[NWARP][32];
    __shared__ int   sidx[32];

    const int tid   = threadIdx.x;
    const int w     = tid >> 5;
    const int lane  = tid & 31;
    const int lbase = blockIdx.x * 32;
    const int l     = lbase + lane;          // one latent per lane
    const int koff  = w * KRANGE;            // this warp's code range

    // Latent row in registers as 32 f32x2 values (loaded directly as 64-bit).
    unsigned long long xr[EDIM / 2];
    {
        const ulonglong2* xrow =
            reinterpret_cast<const ulonglong2*>(x + (size_t)l * EDIM);
        #pragma unroll
        for (int i = 0; i < EDIM / 4; i++) {
            ulonglong2 v = xrow[i];
            xr[2 * i]     = v.x;
            xr[2 * i + 1] = v.y;
        }
    }

    float best = 3.4e38f;
    int   bidx = 0;

    float*       sew = se[w];
    float*       scw = sc[w];

    for (int c0 = 0; c0 < KRANGE; c0 += CH) {
        __syncwarp();   // previous chunk fully consumed by this warp
        // Stage CH codes (coalesced): 4 float4 per lane.
        const float4* src =
            reinterpret_cast<const float4*>(emb + (size_t)(koff + c0) * EDIM);
        #pragma unroll
        for (int i = 0; i < (CH * EDIM / 4) / 32; i++)
            reinterpret_cast<float4*>(sew)[lane + i * 32] = src[lane + i * 32];
        scw[lane] = g_c[koff + c0 + lane];
        __syncwarp();

        #pragma unroll 2
        for (int k = 0; k < CH; k++) {
            const ulonglong2* e2 =
                reinterpret_cast<const ulonglong2*>(sew + k * EDIM);
            unsigned long long a0 = 0ull, a1 = 0ull, a2 = 0ull, a3 = 0ull;
            #pragma unroll
            for (int i = 0; i < 16; i += 2) {
                ulonglong2 ea = e2[i];
                ulonglong2 eb = e2[i + 1];
                a0 = fma2(xr[2 * i],     ea.x, a0);
                a1 = fma2(xr[2 * i + 1], ea.y, a1);
                a2 = fma2(xr[2 * i + 2], eb.x, a2);
                a3 = fma2(xr[2 * i + 3], eb.y, a3);
            }
            unsigned long long s = add2(add2(a0, a1), add2(a2, a3));
            float slo, shi;
            upk2(s, slo, shi);
            float dot   = slo + shi;
            float score = fmaf(-2.0f, dot, scw[k]);   // ||e||^2 - 2 x.e
            if (score < best) { best = score; bidx = koff + c0 + k; }
        }
    }

    // Combine the 4 k-ranges (ascending k order preserves first-min semantics).
    rbest[w][lane] = best;
    ridx[w][lane]  = bidx;
    __syncthreads();
    if (w == 0) {
        float fb = rbest[0][lane];
        int   fi = ridx[0][lane];
        #pragma unroll
        for (int j = 1; j < NWARP; j++) {
            float b2 = rbest[j][lane];
            int   i2 = ridx[j][lane];
            if (b2 < fb) { fb = b2; fi = i2; }
        }
        sidx[lane] = fi;
    }
    __syncthreads();

    // Coalesced epilogue: out = [x | quantized | z_hat | indices], all fp32.
    const size_t LE = (size_t)L_TOTAL * EDIM;
    #pragma unroll 4
    for (int i = tid; i < 32 * EDIM; i += THREADS) {
        int li = i >> 6;          // latent within block
        int e  = i & (EDIM - 1);
        size_t goff = (size_t)(lbase + li) * EDIM + e;
        float xv = x[goff];
        float qv = emb[(size_t)sidx[li] * EDIM + e];
        out[goff]          = xv;
        out[LE + goff]     = qv;
        out[2 * LE + goff] = (xv + qv) - xv;   // mirror x + q - stop_grad(x)
    }
    if (tid < 32)
        out[3 * LE + lbase + tid] = (float)sidx[tid];
}

extern "C" void kernel_launch(void* const* d_in, const int* in_sizes, int n_in,
                              void* d_out, int out_size) {
    const float* x   = (const float*)d_in[0];
    const float* emb = (const float*)d_in[1];
    float* out       = (float*)d_out;

    vq_cnorm_kernel<<<(KQ + 255) / 256, 256>>>(emb);
    vq_main_kernel<<<L_TOTAL / 32, THREADS>>>(x, emb, out);
}